// round 3
// baseline (speedup 1.0000x reference)
#include <cuda_runtime.h>
#include <cuda_bf16.h>

// Problem constants
#define Bn 64
#define Hn 1024
#define Sn 512
#define NT 128            // threads per CTA (main kernel)
#define EPT 8             // Hn / NT rows per thread
#define NW (NT / 32)      // 4 warps
#define TS 4              // steps per register tile
#define NTILE (Sn / TS)   // 128 tiles
#define SPLIT 2           // H-splits for ss precompute

// Precomputed ||s_t||^2 partials: [b][split][t]
__device__ float g_ss[Bn][SPLIT][Sn];

// ---------------------------------------------------------------------------
// Kernel 1: ss[b][t] = sum_h seq[b][h][t]^2  (split over H for occupancy).
// Fully parallel, coalesced along t (the contiguous dim of seq).
// ---------------------------------------------------------------------------
__global__ __launch_bounds__(256)
void ss_kernel(const float* __restrict__ seq) {
    const int b  = blockIdx.x;
    const int sp = blockIdx.y;
    const int t0 = threadIdx.x * 2;              // 256 threads x 2 cols = 512
    const float* base =
        seq + ((size_t)b * Hn + (size_t)sp * (Hn / SPLIT)) * Sn + t0;
    float a0 = 0.f, a1 = 0.f;
#pragma unroll 4
    for (int h = 0; h < Hn / SPLIT; h++) {
        const float2 v = *(const float2*)(base + (size_t)h * Sn);
        a0 = fmaf(v.x, v.x, a0);
        a1 = fmaf(v.y, v.y, a1);
    }
    g_ss[b][sp][t0]     = a0;
    g_ss[b][sp][t0 + 1] = a1;
}

// Two interleaved 5-level butterflies (dot, hh) — single pass through MIO.
__device__ __forceinline__ void warp_sum2(float& x, float& y) {
#pragma unroll
    for (int off = 16; off > 0; off >>= 1) {
        x += __shfl_xor_sync(0xffffffffu, x, off);
        y += __shfl_xor_sync(0xffffffffu, y, off);
    }
}

// ---------------------------------------------------------------------------
// Kernel 2: the serial scan. One CTA (128 threads) per batch.
// ---------------------------------------------------------------------------
__global__ __launch_bounds__(NT)
void orth_add_tsu_kernel(const float* __restrict__ tree,
                         const float* __restrict__ seq,
                         const float* __restrict__ mask,
                         float* __restrict__ out) {
    // Parity-double-buffered per-warp partials (dot / hh), float4-aligned.
    __shared__ __align__(16) float pd[2][NW];
    __shared__ __align__(16) float ph[2][NW];

    const int b    = blockIdx.x;
    const int tid  = threadIdx.x;
    const int wid  = tid >> 5;
    const int lane = tid & 31;

    // Each thread owns rows r = tid + i*NT (coalesced h I/O).
    float h[EPT];
    const float* rowp[EPT];
#pragma unroll
    for (int i = 0; i < EPT; i++) {
        const int r = tid + i * NT;
        h[i]    = tree[b * Hn + r];
        rowp[i] = seq + ((size_t)b * Hn + r) * Sn;
    }
    const float* mrow = mask + (size_t)b * Sn;
    const float* ss0  = &g_ss[b][0][0];
    const float* ss1  = &g_ss[b][1][0];

    // ||h||^2 per-thread partial, maintained incrementally across steps.
    float hhp = 0.f;
#pragma unroll
    for (int i = 0; i < EPT; i++) hhp = fmaf(h[i], h[i], hhp);

    // Double-buffered register tiles: TS=4 consecutive steps per row.
    float cur[EPT][TS], nxt[EPT][TS];
    float mcur[TS], mnxt[TS];
    float scur[TS], snxt[TS];   // precomputed ss per step

#pragma unroll
    for (int i = 0; i < EPT; i++)
        *(float4*)&cur[i][0] = *(const float4*)(rowp[i]);
    *(float4*)&mcur[0] = *(const float4*)(mrow);
    {
        const float4 q0 = *(const float4*)(ss0);
        const float4 q1 = *(const float4*)(ss1);
        scur[0] = q0.x + q1.x; scur[1] = q0.y + q1.y;
        scur[2] = q0.z + q1.z; scur[3] = q0.w + q1.w;
    }

    int p = 0;  // parity of executed (non-skipped) steps

    for (int tile = 0; tile < NTILE; tile++) {
        const int sn   = (tile + 1) * TS;
        const bool more = (tile + 1) < NTILE;
        if (more) {
            // Prefetch next tile — independent of the scan chain.
#pragma unroll
            for (int i = 0; i < EPT; i++)
                *(float4*)&nxt[i][0] = *(const float4*)(rowp[i] + sn);
            *(float4*)&mnxt[0] = *(const float4*)(mrow + sn);
            const float4 q0 = *(const float4*)(ss0 + sn);
            const float4 q1 = *(const float4*)(ss1 + sn);
            snxt[0] = q0.x + q1.x; snxt[1] = q0.y + q1.y;
            snxt[2] = q0.z + q1.z; snxt[3] = q0.w + q1.w;
        }

#pragma unroll
        for (int j = 0; j < TS; j++) {
            const float m = mcur[j];
            // m is uniform across the CTA; m==0 -> identity step, skip all.
            if (m == 0.0f) continue;

            float sv[EPT];
#pragma unroll
            for (int i = 0; i < EPT; i++) sv[i] = cur[i][j];

            // dot partial (hh partial already maintained in hhp).
            float d0 = 0.f, d1 = 0.f;
#pragma unroll
            for (int i = 0; i < EPT; i += 2) {
                d0 = fmaf(h[i],     sv[i],     d0);
                d1 = fmaf(h[i + 1], sv[i + 1], d1);
            }
            float dot = d0 + d1;
            float hh  = hhp;

            warp_sum2(dot, hh);

            if (lane == 0) { pd[p][wid] = dot; ph[p][wid] = hh; }
            __syncthreads();

            // Redundant 4-wide combine on every thread (beats 2nd barrier).
            const float4 vd = *(const float4*)&pd[p][0];
            const float4 vh = *(const float4*)&ph[p][0];
            const float D = (vd.x + vd.y) + (vd.z + vd.w);
            const float A = (vh.x + vh.y) + (vh.z + vh.w);
            p ^= 1;

            // cos = D / max(sqrt(A*ss), eps)  ==  D * rsqrt(max(A*ss, eps^2))
            const float cosv = D * rsqrtf(fmaxf(A * scur[j], 1e-16f));

            // h = clip(h + (s - h*cos), -1, 1)   (m == 1 here)
            float nh = 0.f;
#pragma unroll
            for (int i = 0; i < EPT; i++) {
                const float t  = fmaf(-cosv, h[i], sv[i]);
                float hn = h[i] + t;
                hn = fminf(fmaxf(hn, -1.f), 1.f);
                h[i] = hn;
                nh   = fmaf(hn, hn, nh);
            }
            hhp = nh;
        }

        if (more) {
#pragma unroll
            for (int i = 0; i < EPT; i++)
#pragma unroll
                for (int j = 0; j < TS; j++) cur[i][j] = nxt[i][j];
#pragma unroll
            for (int j = 0; j < TS; j++) { mcur[j] = mnxt[j]; scur[j] = snxt[j]; }
        }
    }

    // Coalesced output write
#pragma unroll
    for (int i = 0; i < EPT; i++) {
        const int r = tid + i * NT;
        out[b * Hn + r] = h[i];
    }
}

extern "C" void kernel_launch(void* const* d_in, const int* in_sizes, int n_in,
                              void* d_out, int out_size) {
    const float* tree = (const float*)d_in[0];  // (B, H)
    const float* seq  = (const float*)d_in[1];  // (B, H, S)
    const float* mask = (const float*)d_in[2];  // (B, S)
    float* out = (float*)d_out;                 // (B, H)
    ss_kernel<<<dim3(Bn, SPLIT), 256>>>(seq);
    orth_add_tsu_kernel<<<Bn, NT>>>(tree, seq, mask, out);
}